// round 6
// baseline (speedup 1.0000x reference)
#include <cuda_runtime.h>
#include <math_constants.h>

#define NN      1024
#define HID     128
#define HEADS   4
#define HD      32
#define LAYERS  3
#define TI      4          // i-rows per block in attention
#define NSEG    4          // j-segments (warp = head x seg)
#define SEGJ    (NN/NSEG)  // 256
#define ADJW    (NN/32)    // 32 words per adjacency row

// ---------------- scratch (no allocs allowed) ----------------
__device__ __align__(128) float    g_h[NN * HID];
__device__ __align__(128) float    g_wlh[NN * HID];
__device__ __align__(128) float    g_wrhT[HID * NN];   // [h*HD+d][j]
__device__ __align__(128) float    g_v[NN * HID];
__device__ __align__(128) float    g_eb[HEADS * NN];   // exp(0.6 * sum_d wrh*att)
__device__ __align__(128) unsigned g_adjbits[ADJW * NN]; // [word][i] transposed
__device__ __align__(128) float    g_pool[64 * HID];   // per-heads-block column partials

// ---------------- adjacency -> bitmask (transposed [w][i]) ----------------
__global__ void adjbits_kernel(const float* __restrict__ adj) {
    int i    = blockIdx.x * 8 + (threadIdx.x >> 5);
    int lane = threadIdx.x & 31;
    for (int w = 0; w < ADJW; w++) {
        float v = adj[(size_t)i * NN + w * 32 + lane];
        unsigned b = __ballot_sync(0xffffffffu, v > 0.5f);
        if (lane == 0) g_adjbits[w * NN + i] = b;
    }
}

// ---------------- input projection: h = relu(nf @ Wp + bp) ----------------
__global__ void proj_kernel(const float* __restrict__ nf,
                            const float* __restrict__ Wp,
                            const float* __restrict__ bp) {
    int i = blockIdx.x;
    int c = threadIdx.x;
    float a = bp[c]
            + nf[i * 3 + 0] * Wp[0 * HID + c]
            + nf[i * 3 + 1] * Wp[1 * HID + c]
            + nf[i * 3 + 2] * Wp[2 * HID + c];
    g_h[i * HID + c] = fmaxf(a, 0.f);
}

// ---------------- 3-way projection GEMM ----------------
// grid (64, 3), block 128, 16 rows per block. y=0 -> wlh, y=1 -> wrhT+eb, y=2 -> v.
__global__ void __launch_bounds__(128)
gemm3_kernel(const float* __restrict__ Wl,
             const float* __restrict__ Wr,
             const float* __restrict__ Wv,
             const float* __restrict__ att) {
    __shared__ float hs[16 * 132];   // stride 132: 16B-aligned float4, conflict-free
    int mode = blockIdx.y;
    const float* W = (mode == 0) ? Wl : (mode == 1 ? Wr : Wv);

    int r0 = blockIdx.x * 16;
    int c  = threadIdx.x;

    for (int t = c; t < 16 * HID; t += 128)
        hs[(t >> 7) * 132 + (t & 127)] = g_h[r0 * HID + t];
    __syncthreads();

    float acc[16];
#pragma unroll
    for (int r = 0; r < 16; r++) acc[r] = 0.f;

#pragma unroll 4
    for (int k4 = 0; k4 < HID / 4; k4++) {
        float w0 = W[(4 * k4 + 0) * HID + c];
        float w1 = W[(4 * k4 + 1) * HID + c];
        float w2 = W[(4 * k4 + 2) * HID + c];
        float w3 = W[(4 * k4 + 3) * HID + c];
#pragma unroll
        for (int r = 0; r < 16; r++) {
            float4 hv = *(const float4*)&hs[r * 132 + 4 * k4];
            acc[r] = fmaf(hv.x, w0, acc[r]);
            acc[r] = fmaf(hv.y, w1, acc[r]);
            acc[r] = fmaf(hv.z, w2, acc[r]);
            acc[r] = fmaf(hv.w, w3, acc[r]);
        }
    }

    if (mode == 0) {
#pragma unroll
        for (int r = 0; r < 16; r++)
            g_wlh[(r0 + r) * HID + c] = acc[r];
    } else if (mode == 2) {
#pragma unroll
        for (int r = 0; r < 16; r++)
            g_v[(r0 + r) * HID + c] = acc[r];
    } else {
        // eb: per head-warp reduce acc[r]*att over d
        int lane = c & 31, hd = c >> 5;
        float atv = att[lane];
#pragma unroll
        for (int r = 0; r < 16; r++) {
            float bv = acc[r] * atv;
#pragma unroll
            for (int o = 16; o; o >>= 1) bv += __shfl_xor_sync(0xffffffffu, bv, o);
            if (lane == 0) g_eb[hd * NN + r0 + r] = __expf(0.6f * bv);
        }
        __syncthreads();
#pragma unroll
        for (int r = 0; r < 16; r++)
            hs[r * 132 + c] = acc[r];
        __syncthreads();
        int l16 = c & 15, grp = c >> 4;   // 8 groups x 16 lanes
        for (int cc = grp; cc < HID; cc += 8)
            g_wrhT[cc * NN + r0 + l16] = hs[l16 * 132 + cc];
    }
}

// ---------------- fused GATv2 attention + merge + LN + residual ----------------
// grid NN/TI = 256 blocks, 512 threads = 16 warps: warp = (head h = w&3, seg = w>>2).
// No online max (softmax shift-invariance; exponent O(+-20), safe in fp32).
// p = eb_j * exp(0.4 * sum |wl+wr| att)  with 0.4 prefolded into att_s.
// Chunk body ordered for load-latency cover: vv0 LDGs issued ~250 instrs
// before their aggregation use; vv1 LDGs issued before the vv0 agg half.
__global__ void __launch_bounds__(512, 2)
attn_kernel(const float* __restrict__ att,
            const float* __restrict__ gamma,
            const float* __restrict__ beta) {
    const int i0   = blockIdx.x * TI;
    const int tid  = threadIdx.x;
    const int warp = tid >> 5;
    const int lane = tid & 31;
    const int h    = warp & 3;
    const int seg  = warp >> 2;

    __shared__ __align__(16) float wl_s[TI][HID];
    __shared__ __align__(16) float att_s[HD];
    __shared__ __align__(16) float p_s[16][32][4];    // [warp][jj][ii]
    __shared__ float s_s[HEADS][NSEG][TI];
    __shared__ float acc_s[HEADS][NSEG][TI][HD];
    __shared__ __align__(16) float agg_s[TI][HID];

    for (int t = tid; t < TI * HID; t += 512)
        wl_s[t >> 7][t & 127] = g_wlh[i0 * HID + t];
    if (tid < HD) att_s[tid] = 0.4f * att[tid];
    __syncthreads();

    float s0 = 0.f, s1 = 0.f, s2 = 0.f, s3 = 0.f;
    float a0 = 0.f, a1 = 0.f, a2 = 0.f, a3 = 0.f;   // acc, lane = d

    const int jbase = seg * SEGJ;
#pragma unroll 1
    for (int c = 0; c < SEGJ / 32; c++) {
        const int j0 = jbase + c * 32;
        const int j  = j0 + lane;

        const float* vb = g_v + (size_t)j0 * HID + h * HD + lane;

        // ---- early: vv0 loads (consumed far below) + scalars ----
        float vv0[16];
#pragma unroll
        for (int jj = 0; jj < 16; jj++)
            vv0[jj] = vb[(size_t)jj * HID];
        float ebv = g_eb[h * NN + j];
        uint4 aw  = *(const uint4*)&g_adjbits[(j0 >> 5) * NN + i0];

        float c0 = 0.f, c1 = 0.f, c2 = 0.f, c3 = 0.f;

        // ---- scores: two half-passes over d ----
#pragma unroll
        for (int half = 0; half < 2; half++) {
            float wr[16];
#pragma unroll
            for (int d = 0; d < 16; d++)
                wr[d] = g_wrhT[(h * HD + half * 16 + d) * NN + j];
#pragma unroll
            for (int q = 0; q < 4; q++) {
                float4 at = *(const float4*)&att_s[half * 16 + 4 * q];
                float w0 = wr[4*q+0], w1 = wr[4*q+1], w2 = wr[4*q+2], w3 = wr[4*q+3];
                const int off = h * HD + half * 16 + 4 * q;
                float4 l;
                l = *(const float4*)&wl_s[0][off];
                c0 = fmaf(fabsf(l.x + w0), at.x, c0); c0 = fmaf(fabsf(l.y + w1), at.y, c0);
                c0 = fmaf(fabsf(l.z + w2), at.z, c0); c0 = fmaf(fabsf(l.w + w3), at.w, c0);
                l = *(const float4*)&wl_s[1][off];
                c1 = fmaf(fabsf(l.x + w0), at.x, c1); c1 = fmaf(fabsf(l.y + w1), at.y, c1);
                c1 = fmaf(fabsf(l.z + w2), at.z, c1); c1 = fmaf(fabsf(l.w + w3), at.w, c1);
                l = *(const float4*)&wl_s[2][off];
                c2 = fmaf(fabsf(l.x + w0), at.x, c2); c2 = fmaf(fabsf(l.y + w1), at.y, c2);
                c2 = fmaf(fabsf(l.z + w2), at.z, c2); c2 = fmaf(fabsf(l.w + w3), at.w, c2);
                l = *(const float4*)&wl_s[3][off];
                c3 = fmaf(fabsf(l.x + w0), at.x, c3); c3 = fmaf(fabsf(l.y + w1), at.y, c3);
                c3 = fmaf(fabsf(l.z + w2), at.z, c3); c3 = fmaf(fabsf(l.w + w3), at.w, c3);
            }
        }

        float p0 = ((aw.x >> lane) & 1u) ? ebv * __expf(c0) : 0.f;
        float p1 = ((aw.y >> lane) & 1u) ? ebv * __expf(c1) : 0.f;
        float p2 = ((aw.z >> lane) & 1u) ? ebv * __expf(c2) : 0.f;
        float p3 = ((aw.w >> lane) & 1u) ? ebv * __expf(c3) : 0.f;
        s0 += p0; s1 += p1; s2 += p2; s3 += p3;

        *(float4*)&p_s[warp][lane][0] = make_float4(p0, p1, p2, p3);
        __syncwarp();

        // ---- vv1 loads issued before vv0 is consumed ----
        float vv1[16];
#pragma unroll
        for (int jj = 0; jj < 16; jj++)
            vv1[jj] = vb[(size_t)(16 + jj) * HID];

        // ---- acc[d=lane] += p[jj] * v[j0+jj, h, lane] ----
#pragma unroll
        for (int jj = 0; jj < 16; jj++) {
            float4 pj = *(const float4*)&p_s[warp][jj][0];
            a0 = fmaf(pj.x, vv0[jj], a0);
            a1 = fmaf(pj.y, vv0[jj], a1);
            a2 = fmaf(pj.z, vv0[jj], a2);
            a3 = fmaf(pj.w, vv0[jj], a3);
        }
#pragma unroll
        for (int jj = 0; jj < 16; jj++) {
            float4 pj = *(const float4*)&p_s[warp][16 + jj][0];
            a0 = fmaf(pj.x, vv1[jj], a0);
            a1 = fmaf(pj.y, vv1[jj], a1);
            a2 = fmaf(pj.z, vv1[jj], a2);
            a3 = fmaf(pj.w, vv1[jj], a3);
        }
        __syncwarp();
    }

    // ---- publish per-segment sums ----
    float sv[4] = {s0, s1, s2, s3};
    float av[4] = {a0, a1, a2, a3};
#pragma unroll
    for (int ii = 0; ii < TI; ii++) {
        float t = sv[ii];
#pragma unroll
        for (int o = 16; o; o >>= 1) t += __shfl_xor_sync(0xffffffffu, t, o);
        if (lane == 0) s_s[h][seg][ii] = t;
        acc_s[h][seg][ii][lane] = av[ii];
    }
    __syncthreads();

    // ---- merge 4 segments per (i, head): warp w handles ii=w>>2, hh=w&3 ----
    {
        int ii = warp >> 2, hh = warp & 3;
        float S = s_s[hh][0][ii] + s_s[hh][1][ii] + s_s[hh][2][ii] + s_s[hh][3][ii];
        float A = acc_s[hh][0][ii][lane] + acc_s[hh][1][ii][lane]
                + acc_s[hh][2][ii][lane] + acc_s[hh][3][ii][lane];
        agg_s[ii][hh * HD + lane] = A / S;
    }
    __syncthreads();

    // ---- LN + relu + residual (warp = row) ----
    if (warp < TI) {
        const int ii = warp;
        float4 x = *(const float4*)&agg_s[ii][lane * 4];
        float m1 = x.x + x.y + x.z + x.w;
        float m2 = x.x*x.x + x.y*x.y + x.z*x.z + x.w*x.w;
#pragma unroll
        for (int o = 16; o; o >>= 1) {
            m1 += __shfl_xor_sync(0xffffffffu, m1, o);
            m2 += __shfl_xor_sync(0xffffffffu, m2, o);
        }
        float mu  = m1 * (1.f / HID);
        float var = m2 * (1.f / HID) - mu * mu;
        float rs  = rsqrtf(var + 1e-5f);
        float4 gm = *(const float4*)&gamma[lane * 4];
        float4 bt = *(const float4*)&beta[lane * 4];
        float4 hv = *(float4*)&g_h[(i0 + ii) * HID + lane * 4];
        hv.x += fmaxf((x.x - mu) * rs * gm.x + bt.x, 0.f);
        hv.y += fmaxf((x.y - mu) * rs * gm.y + bt.y, 0.f);
        hv.z += fmaxf((x.z - mu) * rs * gm.z + bt.z, 0.f);
        hv.w += fmaxf((x.w - mu) * rs * gm.w + bt.w, 0.f);
        *(float4*)&g_h[(i0 + ii) * HID + lane * 4] = hv;
    }
}

// ---------------- node_logits + delta_mu heads + pooling partials ----------------
__global__ void __launch_bounds__(128)
heads_kernel(const float* __restrict__ Wn1, const float* __restrict__ bn1,
             const float* __restrict__ Wn2, const float* __restrict__ bn2,
             const float* __restrict__ Wd1, const float* __restrict__ bd1,
             const float* __restrict__ Wd2, const float* __restrict__ bd2,
             float* __restrict__ out) {
    __shared__ __align__(16) float hs[16][HID];
    __shared__ float redA[4][16], redB[4][16];
    int i0 = blockIdx.x * 16;
    int tid = threadIdx.x;
    int c = tid & 63, g = tid >> 6;

    for (int t = tid; t < 16 * HID; t += 128)
        hs[t >> 7][t & 127] = g_h[i0 * HID + t];
    __syncthreads();

    // pooling partial: column sums of this block's 16 rows
    {
        float ps = 0.f;
#pragma unroll
        for (int r = 0; r < 16; r++) ps += hs[r][tid];
        g_pool[blockIdx.x * HID + tid] = ps;
    }

    const float* W1 = g ? Wd1 : Wn1;
    float bb = g ? bd1[c] : bn1[c];
    float acc[16];
#pragma unroll
    for (int r = 0; r < 16; r++) acc[r] = bb;
#pragma unroll 4
    for (int k4 = 0; k4 < HID / 4; k4++) {
        float w0 = W1[(4 * k4 + 0) * 64 + c];
        float w1 = W1[(4 * k4 + 1) * 64 + c];
        float w2 = W1[(4 * k4 + 2) * 64 + c];
        float w3 = W1[(4 * k4 + 3) * 64 + c];
#pragma unroll
        for (int r = 0; r < 16; r++) {
            float4 hv = *(const float4*)&hs[r][4 * k4];
            acc[r] = fmaf(hv.x, w0, acc[r]);
            acc[r] = fmaf(hv.y, w1, acc[r]);
            acc[r] = fmaf(hv.z, w2, acc[r]);
            acc[r] = fmaf(hv.w, w3, acc[r]);
        }
    }

    float w2a = g ? Wd2[c * 2 + 0] : Wn2[c];
    float w2b = g ? Wd2[c * 2 + 1] : 0.f;
    int warp = tid >> 5, lane = tid & 31;
#pragma unroll
    for (int r = 0; r < 16; r++) {
        float ar = fmaxf(acc[r], 0.f);
        float ya = ar * w2a, yb = ar * w2b;
#pragma unroll
        for (int o = 16; o; o >>= 1) {
            ya += __shfl_xor_sync(0xffffffffu, ya, o);
            yb += __shfl_xor_sync(0xffffffffu, yb, o);
        }
        if (lane == 0) { redA[warp][r] = ya; redB[warp][r] = yb; }
    }
    __syncthreads();

    if (tid < 16) {
        out[i0 + tid] = redA[0][tid] + redA[1][tid] + bn2[0];
    } else if (tid < 32) {
        int r = tid - 16;
        out[NN + 2 * (i0 + r) + 0] = redA[2][r] + redA[3][r] + bd2[0];
        out[NN + 2 * (i0 + r) + 1] = redB[2][r] + redB[3][r] + bd2[1];
    }
}

// ---------------- pooled value head (sums 64 partials) ----------------
__global__ void value_kernel(const float* __restrict__ Wv1, const float* __restrict__ bv1,
                             const float* __restrict__ Wv2, const float* __restrict__ bv2,
                             float* __restrict__ out) { // 1 block, 128 threads
    int t = threadIdx.x;
    __shared__ float ps[HID];
    float s = 0.f;
#pragma unroll 8
    for (int b = 0; b < 64; b++) s += g_pool[b * HID + t];
    ps[t] = s * (1.f / NN);
    __syncthreads();

    float p = 0.f;
    if (t < 64) {
        float a = bv1[t];
        for (int k = 0; k < HID; k++) a = fmaf(ps[k], Wv1[k * 64 + t], a);
        a = fmaxf(a, 0.f);
        p = a * Wv2[t];
    }
#pragma unroll
    for (int o = 16; o; o >>= 1) p += __shfl_xor_sync(0xffffffffu, p, o);
    __shared__ float red[4];
    if ((t & 31) == 0) red[t >> 5] = p;
    __syncthreads();
    if (t == 0) out[NN + 2 * NN] = red[0] + red[1] + red[2] + red[3] + bv2[0];
}

// ---------------- launch ----------------
extern "C" void kernel_launch(void* const* d_in, const int* in_sizes, int n_in,
                              void* d_out, int out_size) {
    const float* nf    = (const float*)d_in[0];
    const float* adj   = (const float*)d_in[1];
    const float* Wp    = (const float*)d_in[2];
    const float* bp    = (const float*)d_in[3];
    const float* Wl    = (const float*)d_in[4];
    const float* Wr    = (const float*)d_in[5];
    const float* Wv    = (const float*)d_in[6];
    const float* att   = (const float*)d_in[7];
    const float* gamma = (const float*)d_in[8];
    const float* beta  = (const float*)d_in[9];
    const float* Wn1   = (const float*)d_in[10];
    const float* bn1   = (const float*)d_in[11];
    const float* Wn2   = (const float*)d_in[12];
    const float* bn2   = (const float*)d_in[13];
    const float* Wd1   = (const float*)d_in[14];
    const float* bd1   = (const float*)d_in[15];
    const float* Wd2   = (const float*)d_in[16];
    const float* bd2   = (const float*)d_in[17];
    const float* Wv1   = (const float*)d_in[18];
    const float* bv1   = (const float*)d_in[19];
    const float* Wv2   = (const float*)d_in[20];
    const float* bv2   = (const float*)d_in[21];
    float* out = (float*)d_out;

    adjbits_kernel<<<128, 256>>>(adj);
    proj_kernel<<<NN, HID>>>(nf, Wp, bp);

    for (int l = 0; l < LAYERS; l++) {
        gemm3_kernel<<<dim3(64, 3), 128>>>(Wl + l * HID * HID,
                                           Wr + l * HID * HID,
                                           Wv + l * HID * HID,
                                           att + l * HD);
        attn_kernel<<<NN / TI, 512>>>(att + l * HD, gamma + l * HID, beta + l * HID);
    }

    heads_kernel<<<64, 128>>>(Wn1, bn1, Wn2, bn2, Wd1, bd1, Wd2, bd2, out);
    value_kernel<<<1, 128>>>(Wv1, bv1, Wv2, bv2, out);
}

// round 7
// speedup vs baseline: 1.1261x; 1.1261x over previous
#include <cuda_runtime.h>
#include <math_constants.h>

#define NN      1024
#define HID     128
#define HEADS   4
#define HD      32
#define LAYERS  3
#define TI      4          // i-rows per block in attention
#define NSEG    4          // j-segments (warp = head x seg)
#define SEGJ    (NN/NSEG)  // 256
#define ADJW    (NN/32)    // 32 words per adjacency row
#define GRID    256
#define TPB     512

// ---------------- scratch (no allocs allowed) ----------------
__device__ __align__(128) float    g_h[NN * HID];
__device__ __align__(128) float    g_wlh[NN * HID];
__device__ __align__(128) float    g_wrhT[HID * NN];     // [h*HD+d][j]
__device__ __align__(128) float    g_v[NN * HID];
__device__ __align__(128) float    g_eb[HEADS * NN];     // exp(0.6 * sum_d wrh*att)
__device__ __align__(128) unsigned g_adjbits[ADJW * NN]; // [word][i] transposed
__device__ __align__(128) float    g_pool[GRID * HID];   // per-block column partials

// ---------------- grid barrier (generation-based, persistent-safe) ----------------
__device__ unsigned          g_cnt = 0;
__device__ volatile unsigned g_gen = 0;

__device__ __forceinline__ void grid_sync() {
    __syncthreads();
    if (threadIdx.x == 0) {
        __threadfence();                       // publish writes + L1 IVALL
        unsigned gen = g_gen;
        if (atomicAdd(&g_cnt, 1) == GRID - 1) {
            g_cnt = 0;
            __threadfence();
            g_gen = gen + 1;
        } else {
            while (g_gen == gen) __nanosleep(32);
        }
        __threadfence();                       // invalidate L1 before new reads
    }
    __syncthreads();
}

// ---------------- shared memory union ----------------
struct AttnSmem {
    float wl[TI][HID];
    float att[HD];
    float p[16][32][4];                 // [warp][jj][ii]
    float s[HEADS][NSEG][TI];
    float acc[HEADS][NSEG][TI][HD];
    float agg[TI][HID];
};
struct GemmSmem  { float hs[16 * 132]; };
struct HeadsSmem { float hs[4][HID]; float redA[4][4]; float redB[4][4]; };
union MegaSmem {
    AttnSmem  a;
    GemmSmem  g;
    HeadsSmem h;
    float     ps[HID];
};

__global__ void __launch_bounds__(TPB, 2)
mega_kernel(const float* __restrict__ nf,   const float* __restrict__ adj,
            const float* __restrict__ Wp,   const float* __restrict__ bp,
            const float* __restrict__ Wl,   const float* __restrict__ Wr,
            const float* __restrict__ Wv,   const float* __restrict__ att,
            const float* __restrict__ gamma,const float* __restrict__ beta,
            const float* __restrict__ Wn1,  const float* __restrict__ bn1,
            const float* __restrict__ Wn2,  const float* __restrict__ bn2,
            const float* __restrict__ Wd1,  const float* __restrict__ bd1,
            const float* __restrict__ Wd2,  const float* __restrict__ bd2,
            const float* __restrict__ Wv1,  const float* __restrict__ bv1,
            const float* __restrict__ Wv2,  const float* __restrict__ bv2,
            float* __restrict__ out) {
    __shared__ MegaSmem sm;
    const int b    = blockIdx.x;
    const int tid  = threadIdx.x;
    const int warp = tid >> 5;
    const int lane = tid & 31;

    // ================= phase 0: proj + adjbits =================
    {
        int t = b * TPB + tid;            // 0..131071
        int i = t >> 7, c = t & 127;
        float a = bp[c]
                + nf[i * 3 + 0] * Wp[0 * HID + c]
                + nf[i * 3 + 1] * Wp[1 * HID + c]
                + nf[i * 3 + 2] * Wp[2 * HID + c];
        g_h[i * HID + c] = fmaxf(a, 0.f);

        int gw  = b * 16 + warp;          // 0..4095
        int row = gw >> 2, part = gw & 3;
#pragma unroll
        for (int q = 0; q < 8; q++) {
            int w2 = part * 8 + q;
            float v = adj[(size_t)row * NN + w2 * 32 + lane];
            unsigned bits = __ballot_sync(0xffffffffu, v > 0.5f);
            if (lane == 0) g_adjbits[w2 * NN + row] = bits;
        }
    }
    grid_sync();

    // ================= layers =================
    for (int l = 0; l < LAYERS; l++) {
        const float* attL = att + l * HD;

        // ---- gemm3 phase: blocks 0..191, 512 threads, 16 rows/block ----
        if (b < 192) {
            int mode = b >> 6;
            int r0   = (b & 63) * 16;
            const float* W = (mode == 0 ? Wl : (mode == 1 ? Wr : Wv)) + l * HID * HID;
            float* hs = sm.g.hs;
            for (int t = tid; t < 16 * HID; t += TPB)
                hs[(t >> 7) * 132 + (t & 127)] = g_h[r0 * HID + t];
            __syncthreads();

            int c = tid & 127, rg = tid >> 7;   // 4 row-groups x 4 rows
            float acc[4] = {0.f, 0.f, 0.f, 0.f};
#pragma unroll 4
            for (int k4 = 0; k4 < HID / 4; k4++) {
                float w0 = W[(4 * k4 + 0) * HID + c];
                float w1 = W[(4 * k4 + 1) * HID + c];
                float w2 = W[(4 * k4 + 2) * HID + c];
                float w3 = W[(4 * k4 + 3) * HID + c];
#pragma unroll
                for (int r = 0; r < 4; r++) {
                    float4 hv = *(const float4*)&hs[(rg * 4 + r) * 132 + 4 * k4];
                    acc[r] = fmaf(hv.x, w0, acc[r]);
                    acc[r] = fmaf(hv.y, w1, acc[r]);
                    acc[r] = fmaf(hv.z, w2, acc[r]);
                    acc[r] = fmaf(hv.w, w3, acc[r]);
                }
            }

            if (mode == 0) {
#pragma unroll
                for (int r = 0; r < 4; r++)
                    g_wlh[(r0 + rg * 4 + r) * HID + c] = acc[r];
            } else if (mode == 2) {
#pragma unroll
                for (int r = 0; r < 4; r++)
                    g_v[(r0 + rg * 4 + r) * HID + c] = acc[r];
            } else {
                // eb: warp covers (rg, head = warp&3), c = head*32 + lane
                int head = warp & 3;
                float atv = attL[lane];
#pragma unroll
                for (int r = 0; r < 4; r++) {
                    float bv = acc[r] * atv;
#pragma unroll
                    for (int o = 16; o; o >>= 1) bv += __shfl_xor_sync(0xffffffffu, bv, o);
                    if (lane == 0) g_eb[head * NN + r0 + rg * 4 + r] = __expf(0.6f * bv);
                }
                __syncthreads();
#pragma unroll
                for (int r = 0; r < 4; r++)
                    hs[(rg * 4 + r) * 132 + c] = acc[r];
                __syncthreads();
                int l16 = tid & 15, grp = tid >> 4;   // 32 groups x 16 lanes
                for (int cc = grp; cc < HID; cc += 32)
                    g_wrhT[cc * NN + r0 + l16] = hs[l16 * 132 + cc];
            }
        }
        grid_sync();

        // ---- attn phase: all 256 blocks (R5 body) ----
        {
            const int i0  = b * TI;
            const int h   = warp & 3;
            const int seg = warp >> 2;

            for (int t = tid; t < TI * HID; t += TPB)
                sm.a.wl[t >> 7][t & 127] = g_wlh[i0 * HID + t];
            if (tid < HD) sm.a.att[tid] = 0.4f * attL[tid];
            __syncthreads();

            float s0 = 0.f, s1 = 0.f, s2 = 0.f, s3 = 0.f;
            float a0 = 0.f, a1 = 0.f, a2 = 0.f, a3 = 0.f;

            const int jbase = seg * SEGJ;
#pragma unroll 1
            for (int c = 0; c < SEGJ / 32; c++) {
                const int j0 = jbase + c * 32;
                const int j  = j0 + lane;

                float ebv = g_eb[h * NN + j];
                uint4 aw  = *(const uint4*)&g_adjbits[(j0 >> 5) * NN + i0];

                float c0 = 0.f, c1 = 0.f, c2 = 0.f, c3 = 0.f;
#pragma unroll
                for (int half = 0; half < 2; half++) {
                    float wr[16];
#pragma unroll
                    for (int d = 0; d < 16; d++)
                        wr[d] = g_wrhT[(h * HD + half * 16 + d) * NN + j];
#pragma unroll
                    for (int q = 0; q < 4; q++) {
                        float4 at = *(const float4*)&sm.a.att[half * 16 + 4 * q];
                        float w0 = wr[4*q+0], w1 = wr[4*q+1], w2 = wr[4*q+2], w3 = wr[4*q+3];
                        const int off = h * HD + half * 16 + 4 * q;
                        float4 lw;
                        lw = *(const float4*)&sm.a.wl[0][off];
                        c0 = fmaf(fabsf(lw.x + w0), at.x, c0); c0 = fmaf(fabsf(lw.y + w1), at.y, c0);
                        c0 = fmaf(fabsf(lw.z + w2), at.z, c0); c0 = fmaf(fabsf(lw.w + w3), at.w, c0);
                        lw = *(const float4*)&sm.a.wl[1][off];
                        c1 = fmaf(fabsf(lw.x + w0), at.x, c1); c1 = fmaf(fabsf(lw.y + w1), at.y, c1);
                        c1 = fmaf(fabsf(lw.z + w2), at.z, c1); c1 = fmaf(fabsf(lw.w + w3), at.w, c1);
                        lw = *(const float4*)&sm.a.wl[2][off];
                        c2 = fmaf(fabsf(lw.x + w0), at.x, c2); c2 = fmaf(fabsf(lw.y + w1), at.y, c2);
                        c2 = fmaf(fabsf(lw.z + w2), at.z, c2); c2 = fmaf(fabsf(lw.w + w3), at.w, c2);
                        lw = *(const float4*)&sm.a.wl[3][off];
                        c3 = fmaf(fabsf(lw.x + w0), at.x, c3); c3 = fmaf(fabsf(lw.y + w1), at.y, c3);
                        c3 = fmaf(fabsf(lw.z + w2), at.z, c3); c3 = fmaf(fabsf(lw.w + w3), at.w, c3);
                    }
                }

                float p0 = ((aw.x >> lane) & 1u) ? ebv * __expf(c0) : 0.f;
                float p1 = ((aw.y >> lane) & 1u) ? ebv * __expf(c1) : 0.f;
                float p2 = ((aw.z >> lane) & 1u) ? ebv * __expf(c2) : 0.f;
                float p3 = ((aw.w >> lane) & 1u) ? ebv * __expf(c3) : 0.f;
                s0 += p0; s1 += p1; s2 += p2; s3 += p3;

                *(float4*)&sm.a.p[warp][lane][0] = make_float4(p0, p1, p2, p3);
                __syncwarp();

                const float* vb = g_v + (size_t)j0 * HID + h * HD + lane;
#pragma unroll
                for (int half = 0; half < 2; half++) {
                    float vv[16];
#pragma unroll
                    for (int jj = 0; jj < 16; jj++)
                        vv[jj] = vb[(size_t)(half * 16 + jj) * HID];
#pragma unroll
                    for (int jj = 0; jj < 16; jj++) {
                        float4 pj = *(const float4*)&sm.a.p[warp][half * 16 + jj][0];
                        a0 = fmaf(pj.x, vv[jj], a0);
                        a1 = fmaf(pj.y, vv[jj], a1);
                        a2 = fmaf(pj.z, vv[jj], a2);
                        a3 = fmaf(pj.w, vv[jj], a3);
                    }
                }
                __syncwarp();
            }

            float sv[4] = {s0, s1, s2, s3};
            float av[4] = {a0, a1, a2, a3};
#pragma unroll
            for (int ii = 0; ii < TI; ii++) {
                float t = sv[ii];
#pragma unroll
                for (int o = 16; o; o >>= 1) t += __shfl_xor_sync(0xffffffffu, t, o);
                if (lane == 0) sm.a.s[h][seg][ii] = t;
                sm.a.acc[h][seg][ii][lane] = av[ii];
            }
            __syncthreads();

            {
                int ii = warp >> 2, hh = warp & 3;
                float S = sm.a.s[hh][0][ii] + sm.a.s[hh][1][ii]
                        + sm.a.s[hh][2][ii] + sm.a.s[hh][3][ii];
                float A = sm.a.acc[hh][0][ii][lane] + sm.a.acc[hh][1][ii][lane]
                        + sm.a.acc[hh][2][ii][lane] + sm.a.acc[hh][3][ii][lane];
                sm.a.agg[ii][hh * HD + lane] = A / S;
            }
            __syncthreads();

            if (warp < TI) {
                const int ii = warp;
                float4 x = *(const float4*)&sm.a.agg[ii][lane * 4];
                float m1 = x.x + x.y + x.z + x.w;
                float m2 = x.x*x.x + x.y*x.y + x.z*x.z + x.w*x.w;
#pragma unroll
                for (int o = 16; o; o >>= 1) {
                    m1 += __shfl_xor_sync(0xffffffffu, m1, o);
                    m2 += __shfl_xor_sync(0xffffffffu, m2, o);
                }
                float mu  = m1 * (1.f / HID);
                float var = m2 * (1.f / HID) - mu * mu;
                float rs  = rsqrtf(var + 1e-5f);
                float4 gm = *(const float4*)&gamma[l * HID + lane * 4];
                float4 bt = *(const float4*)&beta[l * HID + lane * 4];
                float4 hv = *(float4*)&g_h[(i0 + ii) * HID + lane * 4];
                hv.x += fmaxf((x.x - mu) * rs * gm.x + bt.x, 0.f);
                hv.y += fmaxf((x.y - mu) * rs * gm.y + bt.y, 0.f);
                hv.z += fmaxf((x.z - mu) * rs * gm.z + bt.z, 0.f);
                hv.w += fmaxf((x.w - mu) * rs * gm.w + bt.w, 0.f);
                *(float4*)&g_h[(i0 + ii) * HID + lane * 4] = hv;
            }
        }
        grid_sync();
    }

    // ================= heads phase: 4 rows per block =================
    {
        const int i0 = b * 4;
        sm.h.hs[tid >> 7][tid & 127] = g_h[i0 * HID + tid];
        __syncthreads();

        if (tid < HID)
            g_pool[b * HID + tid] = sm.h.hs[0][tid] + sm.h.hs[1][tid]
                                  + sm.h.hs[2][tid] + sm.h.hs[3][tid];

        int sub = tid & 127, rep = tid >> 7;       // rep = row
        int c = sub & 63, g = sub >> 6;
        const float* W1 = g ? Wd1 : Wn1;
        float a = g ? bd1[c] : bn1[c];
#pragma unroll 4
        for (int k4 = 0; k4 < HID / 4; k4++) {
            float4 hv = *(const float4*)&sm.h.hs[rep][4 * k4];
            a = fmaf(hv.x, W1[(4 * k4 + 0) * 64 + c], a);
            a = fmaf(hv.y, W1[(4 * k4 + 1) * 64 + c], a);
            a = fmaf(hv.z, W1[(4 * k4 + 2) * 64 + c], a);
            a = fmaf(hv.w, W1[(4 * k4 + 3) * 64 + c], a);
        }
        a = fmaxf(a, 0.f);
        float w2a = g ? Wd2[c * 2 + 0] : Wn2[c];
        float w2b = g ? Wd2[c * 2 + 1] : 0.f;
        float ya = a * w2a, yb = a * w2b;
#pragma unroll
        for (int o = 16; o; o >>= 1) {
            ya += __shfl_xor_sync(0xffffffffu, ya, o);
            yb += __shfl_xor_sync(0xffffffffu, yb, o);
        }
        int wq = sub >> 5;  // 0..3 (pair g*2 + half)
        if ((sub & 31) == 0) { sm.h.redA[rep][wq] = ya; sm.h.redB[rep][wq] = yb; }
        __syncthreads();

        if (tid < 4) {
            out[i0 + tid] = sm.h.redA[tid][0] + sm.h.redA[tid][1] + bn2[0];
        } else if (tid < 8) {
            int r = tid - 4;
            out[NN + 2 * (i0 + r) + 0] = sm.h.redA[r][2] + sm.h.redA[r][3] + bd2[0];
            out[NN + 2 * (i0 + r) + 1] = sm.h.redB[r][2] + sm.h.redB[r][3] + bd2[1];
        }
    }
    grid_sync();

    // ================= value phase: block 0 =================
    if (b == 0) {
        if (tid < HID) {
            float s = 0.f;
#pragma unroll 8
            for (int bb = 0; bb < GRID; bb++) s += g_pool[bb * HID + tid];
            sm.ps[tid] = s * (1.f / NN);
        }
        __syncthreads();

        float p = 0.f;
        if (tid < 64) {
            float a = bv1[tid];
            for (int k = 0; k < HID; k++) a = fmaf(sm.ps[k], Wv1[k * 64 + tid], a);
            a = fmaxf(a, 0.f);
            p = a * Wv2[tid];
        }
#pragma unroll
        for (int o = 16; o; o >>= 1) p += __shfl_xor_sync(0xffffffffu, p, o);
        __shared__ float red[2];
        if (tid < 64 && (tid & 31) == 0) red[tid >> 5] = p;
        __syncthreads();
        if (tid == 0) out[NN + 2 * NN] = red[0] + red[1] + bv2[0];
    }
}

// ---------------- launch ----------------
extern "C" void kernel_launch(void* const* d_in, const int* in_sizes, int n_in,
                              void* d_out, int out_size) {
    const float* nf    = (const float*)d_in[0];
    const float* adj   = (const float*)d_in[1];
    const float* Wp    = (const float*)d_in[2];
    const float* bp    = (const float*)d_in[3];
    const float* Wl    = (const float*)d_in[4];
    const float* Wr    = (const float*)d_in[5];
    const float* Wv    = (const float*)d_in[6];
    const float* att   = (const float*)d_in[7];
    const float* gamma = (const float*)d_in[8];
    const float* beta  = (const float*)d_in[9];
    const float* Wn1   = (const float*)d_in[10];
    const float* bn1   = (const float*)d_in[11];
    const float* Wn2   = (const float*)d_in[12];
    const float* bn2   = (const float*)d_in[13];
    const float* Wd1   = (const float*)d_in[14];
    const float* bd1   = (const float*)d_in[15];
    const float* Wd2   = (const float*)d_in[16];
    const float* bd2   = (const float*)d_in[17];
    const float* Wv1   = (const float*)d_in[18];
    const float* bv1   = (const float*)d_in[19];
    const float* Wv2   = (const float*)d_in[20];
    const float* bv2   = (const float*)d_in[21];
    float* out = (float*)d_out;

    mega_kernel<<<GRID, TPB>>>(nf, adj, Wp, bp, Wl, Wr, Wv, att, gamma, beta,
                               Wn1, bn1, Wn2, bn2, Wd1, bd1, Wd2, bd2,
                               Wv1, bv1, Wv2, bv2, out);
}

// round 8
// speedup vs baseline: 1.1528x; 1.0237x over previous
#include <cuda_runtime.h>
#include <math_constants.h>

#define NN      1024
#define HID     128
#define HEADS   4
#define HD      32
#define LAYERS  3
#define TI      4          // i-rows per block in attention
#define NSEG    4          // j-segments (warp = head x seg)
#define SEGJ    (NN/NSEG)  // 256
#define ADJW    (NN/32)    // 32 words per adjacency row
#define GRID    256
#define TPB     512

typedef unsigned long long u64;

// ---------------- scratch (no allocs allowed) ----------------
__device__ __align__(128) float    g_h[NN * HID];
__device__ __align__(128) float    g_wlh[NN * HID];
__device__ __align__(128) float    g_wrhT[HID * NN];     // [h*HD+d][j]
__device__ __align__(128) float    g_v[NN * HID];        // pair-interleaved: [(j>>1)][d][j&1]
__device__ __align__(128) float    g_eb[HEADS * NN];     // exp(0.6 * sum_d wrh*att)
__device__ __align__(128) unsigned g_adjbits[ADJW * NN]; // [word][i] transposed
__device__ __align__(128) float    g_pool[GRID * HID];   // per-block column partials

// ---------------- grid barrier (generation-based, persistent-safe) ----------------
__device__ unsigned          g_cnt = 0;
__device__ volatile unsigned g_gen = 0;

__device__ __forceinline__ void grid_sync() {
    __syncthreads();
    if (threadIdx.x == 0) {
        __threadfence();                       // publish writes + L1 IVALL
        unsigned gen = g_gen;
        if (atomicAdd(&g_cnt, 1) == GRID - 1) {
            g_cnt = 0;
            __threadfence();
            g_gen = gen + 1;
        } else {
            while (g_gen == gen) __nanosleep(32);
        }
        __threadfence();                       // invalidate L1 before new reads
    }
    __syncthreads();
}

// ---------------- shared memory union ----------------
struct AttnSmem {
    float wl[TI][HID];
    float att[HD];
    float p[16][TI][32];                // [warp][ii][jj]  (transposed for LDS.64 pairs)
    float s[HEADS][NSEG][TI];
    float acc[HEADS][NSEG][TI][HD];
    float agg[TI][HID];
};
struct GemmSmem  { float hs[16 * 132]; };
struct HeadsSmem { float hs[4][HID]; float redA[4][4]; float redB[4][4]; };
union MegaSmem {
    AttnSmem  a;
    GemmSmem  g;
    HeadsSmem h;
    float     ps[HID];
};

__global__ void __launch_bounds__(TPB, 2)
mega_kernel(const float* __restrict__ nf,   const float* __restrict__ adj,
            const float* __restrict__ Wp,   const float* __restrict__ bp,
            const float* __restrict__ Wl,   const float* __restrict__ Wr,
            const float* __restrict__ Wv,   const float* __restrict__ att,
            const float* __restrict__ gamma,const float* __restrict__ beta,
            const float* __restrict__ Wn1,  const float* __restrict__ bn1,
            const float* __restrict__ Wn2,  const float* __restrict__ bn2,
            const float* __restrict__ Wd1,  const float* __restrict__ bd1,
            const float* __restrict__ Wd2,  const float* __restrict__ bd2,
            const float* __restrict__ Wv1,  const float* __restrict__ bv1,
            const float* __restrict__ Wv2,  const float* __restrict__ bv2,
            float* __restrict__ out) {
    __shared__ MegaSmem sm;
    const int b    = blockIdx.x;
    const int tid  = threadIdx.x;
    const int warp = tid >> 5;
    const int lane = tid & 31;

    // ================= phase 0: proj + adjbits =================
    {
        int t = b * TPB + tid;            // 0..131071
        int i = t >> 7, c = t & 127;
        float a = bp[c]
                + nf[i * 3 + 0] * Wp[0 * HID + c]
                + nf[i * 3 + 1] * Wp[1 * HID + c]
                + nf[i * 3 + 2] * Wp[2 * HID + c];
        g_h[i * HID + c] = fmaxf(a, 0.f);

        int gw  = b * 16 + warp;          // 0..4095
        int row = gw >> 2, part = gw & 3;
#pragma unroll
        for (int q = 0; q < 8; q++) {
            int w2 = part * 8 + q;
            float v = adj[(size_t)row * NN + w2 * 32 + lane];
            unsigned bits = __ballot_sync(0xffffffffu, v > 0.5f);
            if (lane == 0) g_adjbits[w2 * NN + row] = bits;
        }
    }
    grid_sync();

    // ================= layers =================
    for (int l = 0; l < LAYERS; l++) {
        const float* attL = att + l * HD;

        // ---- gemm3 phase: blocks 0..191, 512 threads, 16 rows/block ----
        if (b < 192) {
            int mode = b >> 6;
            int r0   = (b & 63) * 16;
            const float* W = (mode == 0 ? Wl : (mode == 1 ? Wr : Wv)) + l * HID * HID;
            float* hs = sm.g.hs;
            for (int t = tid; t < 16 * HID; t += TPB)
                hs[(t >> 7) * 132 + (t & 127)] = g_h[r0 * HID + t];
            __syncthreads();

            int c = tid & 127, rg = tid >> 7;   // 4 row-groups x 4 rows
            float acc[4] = {0.f, 0.f, 0.f, 0.f};
#pragma unroll 4
            for (int k4 = 0; k4 < HID / 4; k4++) {
                float w0 = W[(4 * k4 + 0) * HID + c];
                float w1 = W[(4 * k4 + 1) * HID + c];
                float w2 = W[(4 * k4 + 2) * HID + c];
                float w3 = W[(4 * k4 + 3) * HID + c];
#pragma unroll
                for (int r = 0; r < 4; r++) {
                    float4 hv = *(const float4*)&hs[(rg * 4 + r) * 132 + 4 * k4];
                    acc[r] = fmaf(hv.x, w0, acc[r]);
                    acc[r] = fmaf(hv.y, w1, acc[r]);
                    acc[r] = fmaf(hv.z, w2, acc[r]);
                    acc[r] = fmaf(hv.w, w3, acc[r]);
                }
            }

            if (mode == 0) {
#pragma unroll
                for (int r = 0; r < 4; r++)
                    g_wlh[(r0 + rg * 4 + r) * HID + c] = acc[r];
            } else if (mode == 2) {
                // pair-interleaved V: [(row>>1)][d][row&1]
#pragma unroll
                for (int r = 0; r < 4; r++) {
                    int row = r0 + rg * 4 + r;
                    g_v[(row >> 1) * (2 * HID) + c * 2 + (row & 1)] = acc[r];
                }
            } else {
                // eb: warp covers (rg, head = warp&3), c = head*32 + lane
                int head = warp & 3;
                float atv = attL[lane];
#pragma unroll
                for (int r = 0; r < 4; r++) {
                    float bv = acc[r] * atv;
#pragma unroll
                    for (int o = 16; o; o >>= 1) bv += __shfl_xor_sync(0xffffffffu, bv, o);
                    if (lane == 0) g_eb[head * NN + r0 + rg * 4 + r] = __expf(0.6f * bv);
                }
                __syncthreads();
#pragma unroll
                for (int r = 0; r < 4; r++)
                    hs[(rg * 4 + r) * 132 + c] = acc[r];
                __syncthreads();
                int l16 = tid & 15, grp = tid >> 4;   // 32 groups x 16 lanes
                for (int cc = grp; cc < HID; cc += 32)
                    g_wrhT[cc * NN + r0 + l16] = hs[l16 * 132 + cc];
            }
        }
        grid_sync();

        // ---- attn phase: all 256 blocks ----
        {
            const int i0  = b * TI;
            const int h   = warp & 3;
            const int seg = warp >> 2;

            for (int t = tid; t < TI * HID; t += TPB)
                sm.a.wl[t >> 7][t & 127] = g_wlh[i0 * HID + t];
            if (tid < HD) sm.a.att[tid] = 0.4f * attL[tid];
            __syncthreads();

            float s0 = 0.f, s1 = 0.f, s2 = 0.f, s3 = 0.f;
            u64 a20 = 0, a21 = 0, a22 = 0, a23 = 0;   // packed even/odd-jj partials

            const int jbase = seg * SEGJ;
#pragma unroll 1
            for (int c = 0; c < SEGJ / 32; c++) {
                const int j0 = jbase + c * 32;
                const int j  = j0 + lane;

                float ebv = g_eb[h * NN + j];
                uint4 aw  = *(const uint4*)&g_adjbits[(j0 >> 5) * NN + i0];

                float c0 = 0.f, c1 = 0.f, c2 = 0.f, c3 = 0.f;
#pragma unroll
                for (int half = 0; half < 2; half++) {
                    float wr[16];
#pragma unroll
                    for (int d = 0; d < 16; d++)
                        wr[d] = g_wrhT[(h * HD + half * 16 + d) * NN + j];
#pragma unroll
                    for (int q = 0; q < 4; q++) {
                        float4 at = *(const float4*)&sm.a.att[half * 16 + 4 * q];
                        float w0 = wr[4*q+0], w1 = wr[4*q+1], w2 = wr[4*q+2], w3 = wr[4*q+3];
                        const int off = h * HD + half * 16 + 4 * q;
                        float4 lw;
                        lw = *(const float4*)&sm.a.wl[0][off];
                        c0 = fmaf(fabsf(lw.x + w0), at.x, c0); c0 = fmaf(fabsf(lw.y + w1), at.y, c0);
                        c0 = fmaf(fabsf(lw.z + w2), at.z, c0); c0 = fmaf(fabsf(lw.w + w3), at.w, c0);
                        lw = *(const float4*)&sm.a.wl[1][off];
                        c1 = fmaf(fabsf(lw.x + w0), at.x, c1); c1 = fmaf(fabsf(lw.y + w1), at.y, c1);
                        c1 = fmaf(fabsf(lw.z + w2), at.z, c1); c1 = fmaf(fabsf(lw.w + w3), at.w, c1);
                        lw = *(const float4*)&sm.a.wl[2][off];
                        c2 = fmaf(fabsf(lw.x + w0), at.x, c2); c2 = fmaf(fabsf(lw.y + w1), at.y, c2);
                        c2 = fmaf(fabsf(lw.z + w2), at.z, c2); c2 = fmaf(fabsf(lw.w + w3), at.w, c2);
                        lw = *(const float4*)&sm.a.wl[3][off];
                        c3 = fmaf(fabsf(lw.x + w0), at.x, c3); c3 = fmaf(fabsf(lw.y + w1), at.y, c3);
                        c3 = fmaf(fabsf(lw.z + w2), at.z, c3); c3 = fmaf(fabsf(lw.w + w3), at.w, c3);
                    }
                }

                float p0 = ((aw.x >> lane) & 1u) ? ebv * __expf(c0) : 0.f;
                float p1 = ((aw.y >> lane) & 1u) ? ebv * __expf(c1) : 0.f;
                float p2 = ((aw.z >> lane) & 1u) ? ebv * __expf(c2) : 0.f;
                float p3 = ((aw.w >> lane) & 1u) ? ebv * __expf(c3) : 0.f;
                s0 += p0; s1 += p1; s2 += p2; s3 += p3;

                // transposed store: p[warp][ii][jj=lane]
                sm.a.p[warp][0][lane] = p0;
                sm.a.p[warp][1][lane] = p1;
                sm.a.p[warp][2][lane] = p2;
                sm.a.p[warp][3][lane] = p3;
                __syncwarp();

                // ---- packed aggregation: even/odd jj pairs, FFMA2 ----
                const float* vp = g_v + (size_t)(j0 >> 1) * (2 * HID) + (h * HD + lane) * 2;
#pragma unroll
                for (int k = 0; k < 16; k++) {
                    u64 vv2 = *(const u64*)(vp + k * (2 * HID));
                    u64 pp0 = *(const u64*)&sm.a.p[warp][0][2 * k];
                    u64 pp1 = *(const u64*)&sm.a.p[warp][1][2 * k];
                    u64 pp2 = *(const u64*)&sm.a.p[warp][2][2 * k];
                    u64 pp3 = *(const u64*)&sm.a.p[warp][3][2 * k];
                    asm("fma.rn.f32x2 %0, %1, %2, %0;" : "+l"(a20) : "l"(pp0), "l"(vv2));
                    asm("fma.rn.f32x2 %0, %1, %2, %0;" : "+l"(a21) : "l"(pp1), "l"(vv2));
                    asm("fma.rn.f32x2 %0, %1, %2, %0;" : "+l"(a22) : "l"(pp2), "l"(vv2));
                    asm("fma.rn.f32x2 %0, %1, %2, %0;" : "+l"(a23) : "l"(pp3), "l"(vv2));
                }
                __syncwarp();
            }

            // unpack packed partials: acc = lo + hi
            float av[4], sv[4] = {s0, s1, s2, s3};
            {
                float lo, hi;
                asm("mov.b64 {%0, %1}, %2;" : "=f"(lo), "=f"(hi) : "l"(a20)); av[0] = lo + hi;
                asm("mov.b64 {%0, %1}, %2;" : "=f"(lo), "=f"(hi) : "l"(a21)); av[1] = lo + hi;
                asm("mov.b64 {%0, %1}, %2;" : "=f"(lo), "=f"(hi) : "l"(a22)); av[2] = lo + hi;
                asm("mov.b64 {%0, %1}, %2;" : "=f"(lo), "=f"(hi) : "l"(a23)); av[3] = lo + hi;
            }
#pragma unroll
            for (int ii = 0; ii < TI; ii++) {
                float t = sv[ii];
#pragma unroll
                for (int o = 16; o; o >>= 1) t += __shfl_xor_sync(0xffffffffu, t, o);
                if (lane == 0) sm.a.s[h][seg][ii] = t;
                sm.a.acc[h][seg][ii][lane] = av[ii];
            }
            __syncthreads();

            {
                int ii = warp >> 2, hh = warp & 3;
                float S = sm.a.s[hh][0][ii] + sm.a.s[hh][1][ii]
                        + sm.a.s[hh][2][ii] + sm.a.s[hh][3][ii];
                float A = sm.a.acc[hh][0][ii][lane] + sm.a.acc[hh][1][ii][lane]
                        + sm.a.acc[hh][2][ii][lane] + sm.a.acc[hh][3][ii][lane];
                sm.a.agg[ii][hh * HD + lane] = A / S;
            }
            __syncthreads();

            if (warp < TI) {
                const int ii = warp;
                float4 x = *(const float4*)&sm.a.agg[ii][lane * 4];
                float m1 = x.x + x.y + x.z + x.w;
                float m2 = x.x*x.x + x.y*x.y + x.z*x.z + x.w*x.w;
#pragma unroll
                for (int o = 16; o; o >>= 1) {
                    m1 += __shfl_xor_sync(0xffffffffu, m1, o);
                    m2 += __shfl_xor_sync(0xffffffffu, m2, o);
                }
                float mu  = m1 * (1.f / HID);
                float var = m2 * (1.f / HID) - mu * mu;
                float rs  = rsqrtf(var + 1e-5f);
                float4 gm = *(const float4*)&gamma[l * HID + lane * 4];
                float4 bt = *(const float4*)&beta[l * HID + lane * 4];
                float4 hv = *(float4*)&g_h[(i0 + ii) * HID + lane * 4];
                hv.x += fmaxf((x.x - mu) * rs * gm.x + bt.x, 0.f);
                hv.y += fmaxf((x.y - mu) * rs * gm.y + bt.y, 0.f);
                hv.z += fmaxf((x.z - mu) * rs * gm.z + bt.z, 0.f);
                hv.w += fmaxf((x.w - mu) * rs * gm.w + bt.w, 0.f);
                *(float4*)&g_h[(i0 + ii) * HID + lane * 4] = hv;
            }
        }
        grid_sync();
    }

    // ================= heads phase: 4 rows per block =================
    {
        const int i0 = b * 4;
        sm.h.hs[tid >> 7][tid & 127] = g_h[i0 * HID + tid];
        __syncthreads();

        if (tid < HID)
            g_pool[b * HID + tid] = sm.h.hs[0][tid] + sm.h.hs[1][tid]
                                  + sm.h.hs[2][tid] + sm.h.hs[3][tid];

        int sub = tid & 127, rep = tid >> 7;       // rep = row
        int c = sub & 63, g = sub >> 6;
        const float* W1 = g ? Wd1 : Wn1;
        float a = g ? bd1[c] : bn1[c];
#pragma unroll 4
        for (int k4 = 0; k4 < HID / 4; k4++) {
            float4 hv = *(const float4*)&sm.h.hs[rep][4 * k4];
            a = fmaf(hv.x, W1[(4 * k4 + 0) * 64 + c], a);
            a = fmaf(hv.y, W1[(4 * k4 + 1) * 64 + c], a);
            a = fmaf(hv.z, W1[(4 * k4 + 2) * 64 + c], a);
            a = fmaf(hv.w, W1[(4 * k4 + 3) * 64 + c], a);
        }
        a = fmaxf(a, 0.f);
        float w2a = g ? Wd2[c * 2 + 0] : Wn2[c];
        float w2b = g ? Wd2[c * 2 + 1] : 0.f;
        float ya = a * w2a, yb = a * w2b;
#pragma unroll
        for (int o = 16; o; o >>= 1) {
            ya += __shfl_xor_sync(0xffffffffu, ya, o);
            yb += __shfl_xor_sync(0xffffffffu, yb, o);
        }
        int wq = sub >> 5;  // 0..3 (pair g*2 + half)
        if ((sub & 31) == 0) { sm.h.redA[rep][wq] = ya; sm.h.redB[rep][wq] = yb; }
        __syncthreads();

        if (tid < 4) {
            out[i0 + tid] = sm.h.redA[tid][0] + sm.h.redA[tid][1] + bn2[0];
        } else if (tid < 8) {
            int r = tid - 4;
            out[NN + 2 * (i0 + r) + 0] = sm.h.redA[r][2] + sm.h.redA[r][3] + bd2[0];
            out[NN + 2 * (i0 + r) + 1] = sm.h.redB[r][2] + sm.h.redB[r][3] + bd2[1];
        }
    }
    grid_sync();

    // ================= value phase: block 0 =================
    if (b == 0) {
        if (tid < HID) {
            float s = 0.f;
#pragma unroll 8
            for (int bb = 0; bb < GRID; bb++) s += g_pool[bb * HID + tid];
            sm.ps[tid] = s * (1.f / NN);
        }
        __syncthreads();

        float p = 0.f;
        if (tid < 64) {
            float a = bv1[tid];
            for (int k = 0; k < HID; k++) a = fmaf(sm.ps[k], Wv1[k * 64 + tid], a);
            a = fmaxf(a, 0.f);
            p = a * Wv2[tid];
        }
#pragma unroll
        for (int o = 16; o; o >>= 1) p += __shfl_xor_sync(0xffffffffu, p, o);
        __shared__ float red[2];
        if (tid < 64 && (tid & 31) == 0) red[tid >> 5] = p;
        __syncthreads();
        if (tid == 0) out[NN + 2 * NN] = red[0] + red[1] + bv2[0];
    }
}

// ---------------- launch ----------------
extern "C" void kernel_launch(void* const* d_in, const int* in_sizes, int n_in,
                              void* d_out, int out_size) {
    const float* nf    = (const float*)d_in[0];
    const float* adj   = (const float*)d_in[1];
    const float* Wp    = (const float*)d_in[2];
    const float* bp    = (const float*)d_in[3];
    const float* Wl    = (const float*)d_in[4];
    const float* Wr    = (const float*)d_in[5];
    const float* Wv    = (const float*)d_in[6];
    const float* att   = (const float*)d_in[7];
    const float* gamma = (const float*)d_in[8];
    const float* beta  = (const float*)d_in[9];
    const float* Wn1   = (const float*)d_in[10];
    const float* bn1   = (const float*)d_in[11];
    const float* Wn2   = (const float*)d_in[12];
    const float* bn2   = (const float*)d_in[13];
    const float* Wd1   = (const float*)d_in[14];
    const float* bd1   = (const float*)d_in[15];
    const float* Wd2   = (const float*)d_in[16];
    const float* bd2   = (const float*)d_in[17];
    const float* Wv1   = (const float*)d_in[18];
    const float* bv1   = (const float*)d_in[19];
    const float* Wv2   = (const float*)d_in[20];
    const float* bv2   = (const float*)d_in[21];
    float* out = (float*)d_out;

    mega_kernel<<<GRID, TPB>>>(nf, adj, Wp, bp, Wl, Wr, Wv, att, gamma, beta,
                               Wn1, bn1, Wn2, bn2, Wd1, bd1, Wd2, bd2,
                               Wv1, bv1, Wv2, bv2, out);
}

// round 9
// speedup vs baseline: 1.1549x; 1.0018x over previous
#include <cuda_runtime.h>
#include <math_constants.h>

#define NN      1024
#define HID     128
#define HEADS   4
#define HD      32
#define LAYERS  3
#define TI      4          // i-rows per block in attention
#define NSEG    4          // j-segments (warp = head x seg)
#define SEGJ    (NN/NSEG)  // 256
#define ADJW    (NN/32)    // 32 words per adjacency row
#define GRID    256
#define TPB     512

typedef unsigned long long u64;

// ---------------- scratch (no allocs allowed) ----------------
__device__ __align__(128) float    g_h[NN * HID];
__device__ __align__(128) float    g_wlh[NN * HID];
__device__ __align__(128) float    g_wrhT[HID * NN];     // pair-interleaved: [h*16+dp][j][2]
__device__ __align__(128) float    g_v[NN * HID];        // pair-interleaved: [(j>>1)][d][j&1]
__device__ __align__(128) float    g_eb[HEADS * NN];     // exp(0.6 * sum_d wrh*att)
__device__ __align__(128) unsigned g_adjbits[ADJW * NN]; // [word][i] transposed
__device__ __align__(128) float    g_pool[GRID * HID];   // per-block column partials

// ---------------- grid barrier (generation-based, persistent-safe) ----------------
__device__ unsigned          g_cnt = 0;
__device__ volatile unsigned g_gen = 0;

__device__ __forceinline__ void grid_sync() {
    __syncthreads();
    if (threadIdx.x == 0) {
        __threadfence();                       // publish writes + L1 IVALL
        unsigned gen = g_gen;
        if (atomicAdd(&g_cnt, 1) == GRID - 1) {
            g_cnt = 0;
            __threadfence();
            g_gen = gen + 1;
        } else {
            while (g_gen == gen) __nanosleep(32);
        }
        __threadfence();                       // invalidate L1 before new reads
    }
    __syncthreads();
}

// ---------------- shared memory union ----------------
struct AttnSmem {
    float wl[TI][HID];
    float att[HD];
    float p[16][TI][32];                // [warp][ii][jj]  (rows 128B; 16B-aligned)
    float s[HEADS][NSEG][TI];
    float acc[HEADS][NSEG][TI][HD];
    float agg[TI][HID];
};
struct GemmSmem  { float hs[16 * 132]; };
struct HeadsSmem { float hs[4][HID]; float redA[4][4]; float redB[4][4]; };
union MegaSmem {
    AttnSmem  a;
    GemmSmem  g;
    HeadsSmem h;
    float     ps[HID];
};

__global__ void __launch_bounds__(TPB, 2)
mega_kernel(const float* __restrict__ nf,   const float* __restrict__ adj,
            const float* __restrict__ Wp,   const float* __restrict__ bp,
            const float* __restrict__ Wl,   const float* __restrict__ Wr,
            const float* __restrict__ Wv,   const float* __restrict__ att,
            const float* __restrict__ gamma,const float* __restrict__ beta,
            const float* __restrict__ Wn1,  const float* __restrict__ bn1,
            const float* __restrict__ Wn2,  const float* __restrict__ bn2,
            const float* __restrict__ Wd1,  const float* __restrict__ bd1,
            const float* __restrict__ Wd2,  const float* __restrict__ bd2,
            const float* __restrict__ Wv1,  const float* __restrict__ bv1,
            const float* __restrict__ Wv2,  const float* __restrict__ bv2,
            float* __restrict__ out) {
    __shared__ MegaSmem sm;
    const int b    = blockIdx.x;
    const int tid  = threadIdx.x;
    const int warp = tid >> 5;
    const int lane = tid & 31;

    // ================= phase 0: proj + adjbits =================
    {
        int t = b * TPB + tid;            // 0..131071
        int i = t >> 7, c = t & 127;
        float a = bp[c]
                + nf[i * 3 + 0] * Wp[0 * HID + c]
                + nf[i * 3 + 1] * Wp[1 * HID + c]
                + nf[i * 3 + 2] * Wp[2 * HID + c];
        g_h[i * HID + c] = fmaxf(a, 0.f);

        int gw  = b * 16 + warp;          // 0..4095
        int row = gw >> 2, part = gw & 3;
#pragma unroll
        for (int q = 0; q < 8; q++) {
            int w2 = part * 8 + q;
            float v = adj[(size_t)row * NN + w2 * 32 + lane];
            unsigned bits = __ballot_sync(0xffffffffu, v > 0.5f);
            if (lane == 0) g_adjbits[w2 * NN + row] = bits;
        }
    }
    grid_sync();

    // ================= layers =================
    for (int l = 0; l < LAYERS; l++) {
        const float* attL = att + l * HD;

        // ---- gemm3 phase: blocks 0..191, 512 threads, 16 rows/block ----
        if (b < 192) {
            int mode = b >> 6;
            int r0   = (b & 63) * 16;
            const float* W = (mode == 0 ? Wl : (mode == 1 ? Wr : Wv)) + l * HID * HID;
            float* hs = sm.g.hs;
            for (int t = tid; t < 16 * HID; t += TPB)
                hs[(t >> 7) * 132 + (t & 127)] = g_h[r0 * HID + t];
            __syncthreads();

            int c = tid & 127, rg = tid >> 7;   // 4 row-groups x 4 rows
            float acc[4] = {0.f, 0.f, 0.f, 0.f};
#pragma unroll 4
            for (int k4 = 0; k4 < HID / 4; k4++) {
                float w0 = W[(4 * k4 + 0) * HID + c];
                float w1 = W[(4 * k4 + 1) * HID + c];
                float w2 = W[(4 * k4 + 2) * HID + c];
                float w3 = W[(4 * k4 + 3) * HID + c];
#pragma unroll
                for (int r = 0; r < 4; r++) {
                    float4 hv = *(const float4*)&hs[(rg * 4 + r) * 132 + 4 * k4];
                    acc[r] = fmaf(hv.x, w0, acc[r]);
                    acc[r] = fmaf(hv.y, w1, acc[r]);
                    acc[r] = fmaf(hv.z, w2, acc[r]);
                    acc[r] = fmaf(hv.w, w3, acc[r]);
                }
            }

            if (mode == 0) {
#pragma unroll
                for (int r = 0; r < 4; r++)
                    g_wlh[(r0 + rg * 4 + r) * HID + c] = acc[r];
            } else if (mode == 2) {
                // pair-interleaved V: [(row>>1)][d][row&1]
#pragma unroll
                for (int r = 0; r < 4; r++) {
                    int row = r0 + rg * 4 + r;
                    g_v[(row >> 1) * (2 * HID) + c * 2 + (row & 1)] = acc[r];
                }
            } else {
                // eb: warp covers (rg, head = warp&3), c = head*32 + lane
                int head = warp & 3;
                float atv = attL[lane];
#pragma unroll
                for (int r = 0; r < 4; r++) {
                    float bv = acc[r] * atv;
#pragma unroll
                    for (int o = 16; o; o >>= 1) bv += __shfl_xor_sync(0xffffffffu, bv, o);
                    if (lane == 0) g_eb[head * NN + r0 + rg * 4 + r] = __expf(0.6f * bv);
                }
                __syncthreads();
#pragma unroll
                for (int r = 0; r < 4; r++)
                    hs[(rg * 4 + r) * 132 + c] = acc[r];
                __syncthreads();
                // pair-interleaved wrhT: [(cc>>1)][j][cc&1]
                int l16 = tid & 15, grp = tid >> 4;   // 32 groups x 16 lanes
                for (int cc = grp; cc < HID; cc += 32)
                    g_wrhT[((cc >> 1) * NN + r0 + l16) * 2 + (cc & 1)] = hs[l16 * 132 + cc];
            }
        }
        grid_sync();

        // ---- attn phase: all 256 blocks ----
        {
            const int i0  = b * TI;
            const int h   = warp & 3;
            const int seg = warp >> 2;

            for (int t = tid; t < TI * HID; t += TPB)
                sm.a.wl[t >> 7][t & 127] = g_wlh[i0 * HID + t];
            if (tid < HD) sm.a.att[tid] = 0.4f * attL[tid];
            __syncthreads();

            float s0 = 0.f, s1 = 0.f, s2 = 0.f, s3 = 0.f;
            u64 a20 = 0, a21 = 0, a22 = 0, a23 = 0;   // packed even/odd-jj partials

            const int jbase = seg * SEGJ;
#pragma unroll 1
            for (int c = 0; c < SEGJ / 32; c++) {
                const int j0 = jbase + c * 32;
                const int j  = j0 + lane;

                float ebv = g_eb[h * NN + j];
                uint4 aw  = *(const uint4*)&g_adjbits[(j0 >> 5) * NN + i0];

                float c0 = 0.f, c1 = 0.f, c2 = 0.f, c3 = 0.f;
#pragma unroll
                for (int half = 0; half < 2; half++) {
                    // pair-interleaved wr loads: LDG.64
                    float2 wr2[8];
#pragma unroll
                    for (int dp = 0; dp < 8; dp++)
                        wr2[dp] = *(const float2*)&g_wrhT[((h * 16 + half * 8 + dp) * NN + j) * 2];
#pragma unroll
                    for (int q = 0; q < 4; q++) {
                        float4 at = *(const float4*)&sm.a.att[half * 16 + 4 * q];
                        float w0 = wr2[2*q].x, w1 = wr2[2*q].y;
                        float w2 = wr2[2*q+1].x, w3 = wr2[2*q+1].y;
                        const int off = h * HD + half * 16 + 4 * q;
                        float4 lw;
                        lw = *(const float4*)&sm.a.wl[0][off];
                        c0 = fmaf(fabsf(lw.x + w0), at.x, c0); c0 = fmaf(fabsf(lw.y + w1), at.y, c0);
                        c0 = fmaf(fabsf(lw.z + w2), at.z, c0); c0 = fmaf(fabsf(lw.w + w3), at.w, c0);
                        lw = *(const float4*)&sm.a.wl[1][off];
                        c1 = fmaf(fabsf(lw.x + w0), at.x, c1); c1 = fmaf(fabsf(lw.y + w1), at.y, c1);
                        c1 = fmaf(fabsf(lw.z + w2), at.z, c1); c1 = fmaf(fabsf(lw.w + w3), at.w, c1);
                        lw = *(const float4*)&sm.a.wl[2][off];
                        c2 = fmaf(fabsf(lw.x + w0), at.x, c2); c2 = fmaf(fabsf(lw.y + w1), at.y, c2);
                        c2 = fmaf(fabsf(lw.z + w2), at.z, c2); c2 = fmaf(fabsf(lw.w + w3), at.w, c2);
                        lw = *(const float4*)&sm.a.wl[3][off];
                        c3 = fmaf(fabsf(lw.x + w0), at.x, c3); c3 = fmaf(fabsf(lw.y + w1), at.y, c3);
                        c3 = fmaf(fabsf(lw.z + w2), at.z, c3); c3 = fmaf(fabsf(lw.w + w3), at.w, c3);
                    }
                }

                float p0 = ((aw.x >> lane) & 1u) ? ebv * __expf(c0) : 0.f;
                float p1 = ((aw.y >> lane) & 1u) ? ebv * __expf(c1) : 0.f;
                float p2 = ((aw.z >> lane) & 1u) ? ebv * __expf(c2) : 0.f;
                float p3 = ((aw.w >> lane) & 1u) ? ebv * __expf(c3) : 0.f;
                s0 += p0; s1 += p1; s2 += p2; s3 += p3;

                // transposed store: p[warp][ii][jj=lane]
                sm.a.p[warp][0][lane] = p0;
                sm.a.p[warp][1][lane] = p1;
                sm.a.p[warp][2][lane] = p2;
                sm.a.p[warp][3][lane] = p3;
                __syncwarp();

                // ---- packed aggregation: LDS.128 p-quads + FFMA2 ----
                const float* vp = g_v + (size_t)(j0 >> 1) * (2 * HID) + (h * HD + lane) * 2;
#pragma unroll
                for (int k = 0; k < 8; k++) {
                    u64 vva = *(const u64*)(vp + (2 * k)     * (2 * HID));
                    u64 vvb = *(const u64*)(vp + (2 * k + 1) * (2 * HID));
                    ulonglong2 q0 = *(const ulonglong2*)&sm.a.p[warp][0][4 * k];
                    ulonglong2 q1 = *(const ulonglong2*)&sm.a.p[warp][1][4 * k];
                    ulonglong2 q2 = *(const ulonglong2*)&sm.a.p[warp][2][4 * k];
                    ulonglong2 q3 = *(const ulonglong2*)&sm.a.p[warp][3][4 * k];
                    asm("fma.rn.f32x2 %0, %1, %2, %0;" : "+l"(a20) : "l"(q0.x), "l"(vva));
                    asm("fma.rn.f32x2 %0, %1, %2, %0;" : "+l"(a21) : "l"(q1.x), "l"(vva));
                    asm("fma.rn.f32x2 %0, %1, %2, %0;" : "+l"(a22) : "l"(q2.x), "l"(vva));
                    asm("fma.rn.f32x2 %0, %1, %2, %0;" : "+l"(a23) : "l"(q3.x), "l"(vva));
                    asm("fma.rn.f32x2 %0, %1, %2, %0;" : "+l"(a20) : "l"(q0.y), "l"(vvb));
                    asm("fma.rn.f32x2 %0, %1, %2, %0;" : "+l"(a21) : "l"(q1.y), "l"(vvb));
                    asm("fma.rn.f32x2 %0, %1, %2, %0;" : "+l"(a22) : "l"(q2.y), "l"(vvb));
                    asm("fma.rn.f32x2 %0, %1, %2, %0;" : "+l"(a23) : "l"(q3.y), "l"(vvb));
                }
                __syncwarp();
            }

            // unpack packed partials: acc = lo + hi
            float av[4], sv[4] = {s0, s1, s2, s3};
            {
                float lo, hi;
                asm("mov.b64 {%0, %1}, %2;" : "=f"(lo), "=f"(hi) : "l"(a20)); av[0] = lo + hi;
                asm("mov.b64 {%0, %1}, %2;" : "=f"(lo), "=f"(hi) : "l"(a21)); av[1] = lo + hi;
                asm("mov.b64 {%0, %1}, %2;" : "=f"(lo), "=f"(hi) : "l"(a22)); av[2] = lo + hi;
                asm("mov.b64 {%0, %1}, %2;" : "=f"(lo), "=f"(hi) : "l"(a23)); av[3] = lo + hi;
            }
#pragma unroll
            for (int ii = 0; ii < TI; ii++) {
                float t = sv[ii];
#pragma unroll
                for (int o = 16; o; o >>= 1) t += __shfl_xor_sync(0xffffffffu, t, o);
                if (lane == 0) sm.a.s[h][seg][ii] = t;
                sm.a.acc[h][seg][ii][lane] = av[ii];
            }
            __syncthreads();

            {
                int ii = warp >> 2, hh = warp & 3;
                float S = sm.a.s[hh][0][ii] + sm.a.s[hh][1][ii]
                        + sm.a.s[hh][2][ii] + sm.a.s[hh][3][ii];
                float A = sm.a.acc[hh][0][ii][lane] + sm.a.acc[hh][1][ii][lane]
                        + sm.a.acc[hh][2][ii][lane] + sm.a.acc[hh][3][ii][lane];
                sm.a.agg[ii][hh * HD + lane] = A / S;
            }
            __syncthreads();

            if (warp < TI) {
                const int ii = warp;
                float4 x = *(const float4*)&sm.a.agg[ii][lane * 4];
                float m1 = x.x + x.y + x.z + x.w;
                float m2 = x.x*x.x + x.y*x.y + x.z*x.z + x.w*x.w;
#pragma unroll
                for (int o = 16; o; o >>= 1) {
                    m1 += __shfl_xor_sync(0xffffffffu, m1, o);
                    m2 += __shfl_xor_sync(0xffffffffu, m2, o);
                }
                float mu  = m1 * (1.f / HID);
                float var = m2 * (1.f / HID) - mu * mu;
                float rs  = rsqrtf(var + 1e-5f);
                float4 gm = *(const float4*)&gamma[l * HID + lane * 4];
                float4 bt = *(const float4*)&beta[l * HID + lane * 4];
                float4 hv = *(float4*)&g_h[(i0 + ii) * HID + lane * 4];
                hv.x += fmaxf((x.x - mu) * rs * gm.x + bt.x, 0.f);
                hv.y += fmaxf((x.y - mu) * rs * gm.y + bt.y, 0.f);
                hv.z += fmaxf((x.z - mu) * rs * gm.z + bt.z, 0.f);
                hv.w += fmaxf((x.w - mu) * rs * gm.w + bt.w, 0.f);
                *(float4*)&g_h[(i0 + ii) * HID + lane * 4] = hv;
            }
        }
        grid_sync();
    }

    // ================= heads phase: 4 rows per block =================
    {
        const int i0 = b * 4;
        sm.h.hs[tid >> 7][tid & 127] = g_h[i0 * HID + tid];
        __syncthreads();

        if (tid < HID)
            g_pool[b * HID + tid] = sm.h.hs[0][tid] + sm.h.hs[1][tid]
                                  + sm.h.hs[2][tid] + sm.h.hs[3][tid];

        int sub = tid & 127, rep = tid >> 7;       // rep = row
        int c = sub & 63, g = sub >> 6;
        const float* W1 = g ? Wd1 : Wn1;
        float a = g ? bd1[c] : bn1[c];
#pragma unroll 4
        for (int k4 = 0; k4 < HID / 4; k4++) {
            float4 hv = *(const float4*)&sm.h.hs[rep][4 * k4];
            a = fmaf(hv.x, W1[(4 * k4 + 0) * 64 + c], a);
            a = fmaf(hv.y, W1[(4 * k4 + 1) * 64 + c], a);
            a = fmaf(hv.z, W1[(4 * k4 + 2) * 64 + c], a);
            a = fmaf(hv.w, W1[(4 * k4 + 3) * 64 + c], a);
        }
        a = fmaxf(a, 0.f);
        float w2a = g ? Wd2[c * 2 + 0] : Wn2[c];
        float w2b = g ? Wd2[c * 2 + 1] : 0.f;
        float ya = a * w2a, yb = a * w2b;
#pragma unroll
        for (int o = 16; o; o >>= 1) {
            ya += __shfl_xor_sync(0xffffffffu, ya, o);
            yb += __shfl_xor_sync(0xffffffffu, yb, o);
        }
        int wq = sub >> 5;  // 0..3 (pair g*2 + half)
        if ((sub & 31) == 0) { sm.h.redA[rep][wq] = ya; sm.h.redB[rep][wq] = yb; }
        __syncthreads();

        if (tid < 4) {
            out[i0 + tid] = sm.h.redA[tid][0] + sm.h.redA[tid][1] + bn2[0];
        } else if (tid < 8) {
            int r = tid - 4;
            out[NN + 2 * (i0 + r) + 0] = sm.h.redA[r][2] + sm.h.redA[r][3] + bd2[0];
            out[NN + 2 * (i0 + r) + 1] = sm.h.redB[r][2] + sm.h.redB[r][3] + bd2[1];
        }
    }
    grid_sync();

    // ================= value phase: block 0 =================
    if (b == 0) {
        if (tid < HID) {
            float s = 0.f;
#pragma unroll 8
            for (int bb = 0; bb < GRID; bb++) s += g_pool[bb * HID + tid];
            sm.ps[tid] = s * (1.f / NN);
        }
        __syncthreads();

        float p = 0.f;
        if (tid < 64) {
            float a = bv1[tid];
            for (int k = 0; k < HID; k++) a = fmaf(sm.ps[k], Wv1[k * 64 + tid], a);
            a = fmaxf(a, 0.f);
            p = a * Wv2[tid];
        }
#pragma unroll
        for (int o = 16; o; o >>= 1) p += __shfl_xor_sync(0xffffffffu, p, o);
        __shared__ float red[2];
        if (tid < 64 && (tid & 31) == 0) red[tid >> 5] = p;
        __syncthreads();
        if (tid == 0) out[NN + 2 * NN] = red[0] + red[1] + bv2[0];
    }
}

// ---------------- launch ----------------
extern "C" void kernel_launch(void* const* d_in, const int* in_sizes, int n_in,
                              void* d_out, int out_size) {
    const float* nf    = (const float*)d_in[0];
    const float* adj   = (const float*)d_in[1];
    const float* Wp    = (const float*)d_in[2];
    const float* bp    = (const float*)d_in[3];
    const float* Wl    = (const float*)d_in[4];
    const float* Wr    = (const float*)d_in[5];
    const float* Wv    = (const float*)d_in[6];
    const float* att   = (const float*)d_in[7];
    const float* gamma = (const float*)d_in[8];
    const float* beta  = (const float*)d_in[9];
    const float* Wn1   = (const float*)d_in[10];
    const float* bn1   = (const float*)d_in[11];
    const float* Wn2   = (const float*)d_in[12];
    const float* bn2   = (const float*)d_in[13];
    const float* Wd1   = (const float*)d_in[14];
    const float* bd1   = (const float*)d_in[15];
    const float* Wd2   = (const float*)d_in[16];
    const float* bd2   = (const float*)d_in[17];
    const float* Wv1   = (const float*)d_in[18];
    const float* bv1   = (const float*)d_in[19];
    const float* Wv2   = (const float*)d_in[20];
    const float* bv2   = (const float*)d_in[21];
    float* out = (float*)d_out;

    mega_kernel<<<GRID, TPB>>>(nf, adj, Wp, bp, Wl, Wr, Wv, att, gamma, beta,
                               Wn1, bn1, Wn2, bn2, Wd1, bd1, Wd2, bd2,
                               Wv1, bv1, Wv2, bv2, out);
}